// round 14
// baseline (speedup 1.0000x reference)
#include <cuda_runtime.h>
#include <cuda_fp16.h>
#include <math.h>
#include <stdint.h>

#define B_ 32
#define T_ 2048
#define E_ 1024
#define A_ 1024
#define D_ 1024

typedef unsigned int u32;
typedef unsigned long long u64;

// ---------------- scratch (device globals; allocations forbidden) --------------
__device__ __align__(256) __half g_enc_h[(size_t)B_ * T_ * E_];  // enc fp16
__device__ __align__(256) __half g_Wt[A_ * E_];                  // W^T [A,E] fp16
__device__ float g_dec_proj[B_ * A_];
__device__ float g_epart[8 * B_ * T_];     // per-N-chunk energy partials
__device__ float g_ctx_part[8 * B_ * E_];

// ---------------- PTX helpers (baseline ISA only: sm_80-class) ------------------
__device__ __forceinline__ u32 smem_u32(const void* p) {
    u32 a; asm("{ .reg .u64 t; cvta.to.shared.u64 t, %1; cvt.u32.u64 %0, t; }" : "=r"(a) : "l"(p));
    return a;
}
__device__ __forceinline__ void cpa16(u32 dst, const void* src) {
    asm volatile("cp.async.cg.shared.global [%0], [%1], 16;" :: "r"(dst), "l"(src));
}
#define CPA_COMMIT()  asm volatile("cp.async.commit_group;" ::: "memory")
#define CPA_WAIT(n)   asm volatile("cp.async.wait_group %0;" :: "n"(n) : "memory")

__device__ __forceinline__ void ldsm4(u32* r, u32 addr) {
    asm volatile("ldmatrix.sync.aligned.m8n8.x4.shared.b16 {%0,%1,%2,%3}, [%4];"
        : "=r"(r[0]), "=r"(r[1]), "=r"(r[2]), "=r"(r[3]) : "r"(addr));
}
__device__ __forceinline__ void mma_f16(float* c, const u32* a, const u32* b) {
    asm volatile("mma.sync.aligned.m16n8k16.row.col.f32.f16.f16.f32 "
        "{%0,%1,%2,%3}, {%4,%5,%6,%7}, {%8,%9}, {%0,%1,%2,%3};"
        : "+f"(c[0]), "+f"(c[1]), "+f"(c[2]), "+f"(c[3])
        : "r"(a[0]), "r"(a[1]), "r"(a[2]), "r"(a[3]), "r"(b[0]), "r"(b[1]));
}

// tanh via 2 MUFU: tanh(x) = (e - 1)/(e + 1), e = 2^(2x*log2e)
__device__ __forceinline__ float fast_tanh(float x) {
    float xa = fminf(fmaxf(x, -12.0f), 12.0f);
    float e;
    asm("ex2.approx.f32 %0, %1;" : "=f"(e) : "f"(xa * 2.8853900817779268f));
    float r;
    asm("rcp.approx.f32 %0, %1;" : "=f"(r) : "f"(e + 1.0f));
    return (e - 1.0f) * r;
}

// ---------------- pass 0a: enc fp32 -> fp16 (8 elems/thread, 16B store) ---------
__global__ __launch_bounds__(256) void convert_enc_kernel(const float* __restrict__ enc) {
    size_t i = ((size_t)blockIdx.x * 256 + threadIdx.x) * 8;
    float4 x = *(const float4*)(enc + i);
    float4 y = *(const float4*)(enc + i + 4);
    __half2 h[4] = { __floats2half2_rn(x.x, x.y), __floats2half2_rn(x.z, x.w),
                     __floats2half2_rn(y.x, y.y), __floats2half2_rn(y.z, y.w) };
    *(uint4*)(g_enc_h + i) = *(uint4*)h;
}

// ---------------- pass 0b: W_enc [E,A] -> W^T [A,E] fp16 (RN) -------------------
__global__ __launch_bounds__(256) void convert_wt_kernel(const float* __restrict__ W) {
    int idx = blockIdx.x * 256 + threadIdx.x;      // output-linear over [A,E]
    int a = idx >> 10, e = idx & 1023;
    g_Wt[idx] = __float2half_rn(W[(size_t)e * A_ + a]);
}

// ---------------- pass 1: dec_proj[b,a] = dec[b,:] . W_dec[:,a] + b_enc[a] ------
__global__ __launch_bounds__(256) void dec_proj_kernel(
    const float* __restrict__ dec_out, const float* __restrict__ W_dec,
    const float* __restrict__ b_enc)
{
    int b = blockIdx.y;
    int a = blockIdx.x * 256 + threadIdx.x;
    __shared__ float ds[D_];
    for (int i = threadIdx.x; i < D_; i += 256) ds[i] = dec_out[b * D_ + i];
    __syncthreads();
    float s = b_enc[a];
    #pragma unroll 8
    for (int d = 0; d < D_; ++d) s += ds[d] * W_dec[(size_t)d * A_ + a];
    g_dec_proj[b * A_ + a] = s;
}

// ---------------- pass 2: fp16 mma.sync GEMM, 64x64 warp tiles ------------------
// 256 thr = 8 warps as 4M x 2N, warp tile 64x64, CTA tile 256x128 per item.
// 1 CTA/SM with ~256 regs/thread budget => 128 fp32 accumulators/thread fit.
// LDSM bytes/MAC drops 0.094 -> 0.0625: crossbar (88KB/stage) now under the
// tensor-pipe time (~970cyc) => tensor-bound. Items (m-tile 256, N-chunk 128):
// 2048 over 152 CTAs. KC=32 stages, depth-4 cp.async ring (always-commit),
// one __syncthreads/stage. Rows 64B, granule-XOR swizzle, ks flip = XOR 32.
#define MT 256
#define NITEM 2048
#define GRID_E 152
#define NPIPE 4
#define ROWB 64
#define A_SZ (MT * ROWB)             // 16384
#define B_SZ (128 * ROWB)            // 8192
#define STG_SZ (A_SZ + B_SZ)         // 24576
#define ST_A 0
#define ST_B A_SZ
#define OF_V  (NPIPE * STG_SZ)       // 98304
#define OF_RED (OF_V + 4096)
#define SMEM_TOTAL (OF_RED + 2048)   // 104448 -> 1 CTA of 256 thr/SM

__global__ __launch_bounds__(256, 1) void energy_kernel(const float* __restrict__ v) {
    extern __shared__ char smem[];
    u32 sb = smem_u32(smem);
    const int tid  = threadIdx.x;
    const int lane = tid & 31, wid = tid >> 5;
    const int wm = wid >> 1, wn = wid & 1;       // 4M x 2N warp grid, tile 64x64

    const u32 cta = blockIdx.x;
    const u32 w0 = (cta * NITEM) / GRID_E;
    const u32 w1 = ((cta + 1) * NITEM) / GRID_E;
    const u32 nst = (w1 - w0) * 32;

    float* v_s  = (float*)(smem + OF_V);
    float* red  = (float*)(smem + OF_RED);
    for (int i = tid; i < A_; i += 256) v_s[i] = v[i];

    // ---- per-thread constant addressing ----
    // stage_in: A = 1024 chunks (4/thread), B = 512 chunks (2/thread)
    u32 soA[4], cgA[4], soB[2], cgB[2];
    #pragma unroll
    for (int r = 0; r < 4; ++r) {
        int c = tid + r * 256, row = c >> 2, g = c & 3;
        soA[r] = (u32)(row * ROWB + ((g ^ (row >> 1)) & 3) * 16);
        cgA[r] = (u32)(row * 2048 + g * 16);
    }
    #pragma unroll
    for (int r = 0; r < 2; ++r) {
        int c = tid + r * 256, row = c >> 2, g = c & 3;
        soB[r] = (u32)(row * ROWB + ((g ^ (row >> 1)) & 3) * 16);
        cgB[r] = (u32)(row * 2048 + g * 16);
    }

    // ldsm constants (ks=0; ks=1 = off ^ 32)
    const u32 a_gbit = (u32)((lane >> 4) & 1);
    const u32 b_gbit = (u32)((lane >> 3) & 1);
    u32 loA[4], loB[4];
    #pragma unroll
    for (int tm = 0; tm < 4; ++tm) {
        int r = wm * 64 + (lane & 15) + tm * 16;
        loA[tm] = (u32)(r * ROWB) + ((a_gbit ^ ((u32)(r >> 1) & 3)) & 3) * 16;
    }
    #pragma unroll
    for (int p = 0; p < 4; ++p) {
        int r = wn * 64 + (lane & 7) + ((lane >> 4) & 1) * 8 + p * 16;
        loB[p] = (u32)(r * ROWB) + ((b_gbit ^ ((u32)(r >> 1) & 3)) & 3) * 16;
    }

    auto stage_in = [&](u32 f) {
        const u32 w  = w0 + (f >> 5);
        const u32 base = sb + (f & 3) * STG_SZ;
        const u32 kbyte = (f & 31) * 64;
        const char* encp = (const char*)g_enc_h + ((size_t)(w >> 3) << 19);
        const char* wp   = (const char*)g_Wt + ((size_t)(w & 7) << 18);
        #pragma unroll
        for (int r = 0; r < 4; ++r) cpa16(base + ST_A + soA[r], encp + cgA[r] + kbyte);
        #pragma unroll
        for (int r = 0; r < 2; ++r) cpa16(base + ST_B + soB[r], wp + cgB[r] + kbyte);
    };

    // prologue
    #pragma unroll
    for (u32 p = 0; p < NPIPE - 1; ++p) {
        stage_in(p);
        CPA_COMMIT();
    }

    for (u32 w = w0; w < w1; ++w) {
        const int m0 = (int)(w >> 3) << 8;
        const int ch = (int)(w & 7);
        const int b  = m0 >> 11;
        const int a0 = ch * 128;

        float c_[4][8][4];           // 128 fp32 accumulators (64x64 warp tile)
        #pragma unroll
        for (int tm = 0; tm < 4; ++tm)
            #pragma unroll
            for (int tn = 0; tn < 8; ++tn)
                #pragma unroll
                for (int q = 0; q < 4; ++q) c_[tm][tn][q] = 0.f;

        for (u32 kc = 0; kc < 32; ++kc) {
            const u32 f = (w - w0) * 32 + kc;
            CPA_WAIT(2);
            __syncthreads();

            if (f + NPIPE - 1 < nst) stage_in(f + NPIPE - 1);
            CPA_COMMIT();            // possibly-empty group keeps wait(2) exact

            const u32 baseA = sb + (f & 3) * STG_SZ + ST_A;
            const u32 baseB = sb + (f & 3) * STG_SZ + ST_B;
            #pragma unroll
            for (int ks = 0; ks < 2; ++ks) {
                const u32 kx = (u32)(ks * 32);
                u32 ah[4][4];
                #pragma unroll
                for (int tm = 0; tm < 4; ++tm)
                    ldsm4(ah[tm], baseA + (loA[tm] ^ kx));
                #pragma unroll
                for (int p = 0; p < 4; ++p) {
                    u32 tb[4];
                    ldsm4(tb, baseB + (loB[p] ^ kx));
                    #pragma unroll
                    for (int tm = 0; tm < 4; ++tm) {
                        mma_f16(c_[tm][2*p],   ah[tm], tb);
                        mma_f16(c_[tm][2*p+1], ah[tm], tb + 2);
                    }
                }
            }
        }

        // epilogue: tanh(c + dec_proj) . v ; rows = wm*64 + tm*16 + (lane>>2)(+8)
        float rowsum[8];
        #pragma unroll
        for (int i = 0; i < 8; ++i) rowsum[i] = 0.f;
        const int nbase = a0 + wn * 64 + 2 * (lane & 3);
        #pragma unroll
        for (int tn = 0; tn < 8; ++tn) {
            int n = nbase + tn * 8;
            float2 d = *(const float2*)&g_dec_proj[b * A_ + n];
            float2 vv = *(const float2*)&v_s[n];
            #pragma unroll
            for (int tm = 0; tm < 4; ++tm) {
                rowsum[tm*2+0] += fast_tanh(c_[tm][tn][0] + d.x) * vv.x
                                + fast_tanh(c_[tm][tn][1] + d.y) * vv.y;
                rowsum[tm*2+1] += fast_tanh(c_[tm][tn][2] + d.x) * vv.x
                                + fast_tanh(c_[tm][tn][3] + d.y) * vv.y;
            }
        }
        #pragma unroll
        for (int i = 0; i < 8; ++i) {
            float s = rowsum[i];
            s += __shfl_xor_sync(0xffffffffu, s, 1);
            s += __shfl_xor_sync(0xffffffffu, s, 2);
            rowsum[i] = s;
        }
        if ((lane & 3) == 0) {
            int r0 = lane >> 2;
            int rb = wn * 256 + wm * 64;
            #pragma unroll
            for (int tm = 0; tm < 4; ++tm) {
                red[rb + tm * 16 + r0]     = rowsum[tm*2+0];
                red[rb + tm * 16 + r0 + 8] = rowsum[tm*2+1];
            }
        }
        __syncthreads();
        g_epart[ch * (B_ * T_) + m0 + tid] = red[tid] + red[256 + tid];
    }
}

// ---------------- pass 3: sum chunk partials + masked (0/1) softmax -------------
__global__ __launch_bounds__(256) void softmax_kernel(
    const int* __restrict__ x_lens, float* __restrict__ att)
{
    int b = blockIdx.x, tid = threadIdx.x;
    __shared__ float sm[T_];
    __shared__ float red[256];
    int len = x_lens[b];

    float mx = -3.4e38f;
    for (int t = tid; t < T_; t += 256) {
        int r = b * T_ + t;
        float e = 0.f;
        #pragma unroll
        for (int ch = 0; ch < 8; ++ch) e += g_epart[ch * (B_ * T_) + r];
        e = (t < len) ? e : 0.0f;      // reference multiplies by 0/1 mask
        sm[t] = e;
        mx = fmaxf(mx, e);
    }
    red[tid] = mx; __syncthreads();
    for (int s = 128; s > 0; s >>= 1) {
        if (tid < s) red[tid] = fmaxf(red[tid], red[tid + s]);
        __syncthreads();
    }
    mx = red[0];
    __syncthreads();

    float lsum = 0.f;
    for (int t = tid; t < T_; t += 256) {
        float e = expf(sm[t] - mx);
        sm[t] = e;
        lsum += e;
    }
    red[tid] = lsum; __syncthreads();
    for (int s = 128; s > 0; s >>= 1) {
        if (tid < s) red[tid] += red[tid + s];
        __syncthreads();
    }
    float inv = 1.0f / red[0];
    for (int t = tid; t < T_; t += 256) att[b * T_ + t] = sm[t] * inv;
}

// ---------------- pass 4: context partials over 8 T-segments (fp16 enc) ---------
__global__ __launch_bounds__(256) void context_part_kernel(const float* __restrict__ att) {
    int b = blockIdx.y, seg = blockIdx.z;
    int e2 = threadIdx.x;                        // + 256 for second column
    __shared__ float as_[T_ / 8];
    int t0 = seg * (T_ / 8);
    as_[threadIdx.x] = att[b * T_ + t0 + threadIdx.x];
    __syncthreads();
    const __half2* ep = (const __half2*)g_enc_h + ((size_t)b * T_ + t0) * (E_ / 2);
    float s0 = 0.f, s1 = 0.f, s2 = 0.f, s3 = 0.f;
    #pragma unroll 8
    for (int t = 0; t < T_ / 8; ++t) {
        const __half2* row = ep + (size_t)t * (E_ / 2);
        float2 f0 = __half22float2(row[e2]);
        float2 f1 = __half22float2(row[e2 + 256]);
        float a = as_[t];
        s0 += f0.x * a; s1 += f0.y * a;
        s2 += f1.x * a; s3 += f1.y * a;
    }
    float2* out = (float2*)&g_ctx_part[((size_t)seg * B_ + b) * E_];
    out[e2]       = make_float2(s0, s1);
    out[e2 + 256] = make_float2(s2, s3);
}

__global__ __launch_bounds__(256) void context_reduce_kernel(float* __restrict__ ctx) {
    int i = blockIdx.x * 256 + threadIdx.x;      // over B_*E_
    float s = 0.f;
    #pragma unroll
    for (int seg = 0; seg < 8; ++seg) s += g_ctx_part[seg * (B_ * E_) + i];
    ctx[i] = s;
}

// ---------------- launch -------------------------------------------------------
extern "C" void kernel_launch(void* const* d_in, const int* in_sizes, int n_in,
                              void* d_out, int out_size)
{
    const float* enc     = (const float*)d_in[0];  // [B,T,E]
    const int*   x_lens  = (const int*)  d_in[1];  // [B]
    const float* dec_out = (const float*)d_in[2];  // [B,1,D]
    // d_in[3] att_weights_step: unused by reference
    const float* W_enc   = (const float*)d_in[4];  // [E,A]
    const float* b_enc   = (const float*)d_in[5];  // [A]
    const float* W_dec   = (const float*)d_in[6];  // [D,A]
    const float* v       = (const float*)d_in[7];  // [A]

    float* ctx = (float*)d_out;            // [B,1,E]
    float* att = (float*)d_out + B_ * E_;  // [B,T]

    cudaFuncSetAttribute(energy_kernel,
                         cudaFuncAttributeMaxDynamicSharedMemorySize, SMEM_TOTAL);

    convert_enc_kernel<<<(B_ * T_ * E_) / (256 * 8), 256>>>(enc);
    convert_wt_kernel <<<(A_ * E_) / 256, 256>>>(W_enc);
    dec_proj_kernel   <<<dim3(A_ / 256, B_), 256>>>(dec_out, W_dec, b_enc);
    energy_kernel     <<<GRID_E, 256, SMEM_TOTAL>>>(v);
    softmax_kernel    <<<B_, 256>>>(x_lens, att);
    context_part_kernel<<<dim3(1, B_, 8), 256>>>(att);
    context_reduce_kernel<<<(B_ * E_) / 256, 256>>>(ctx);
}

// round 15
// speedup vs baseline: 1.1312x; 1.1312x over previous
#include <cuda_runtime.h>
#include <cuda_fp16.h>
#include <math.h>
#include <stdint.h>

#define B_ 32
#define T_ 2048
#define E_ 1024
#define A_ 1024
#define D_ 1024

typedef unsigned int u32;
typedef unsigned long long u64;

// ---------------- scratch (device globals; allocations forbidden) --------------
__device__ __align__(256) __half g_enc_h[(size_t)B_ * T_ * E_];  // enc fp16
__device__ __align__(256) __half g_Wt[A_ * E_];                  // W^T [A,E] fp16
__device__ float g_dec_proj[B_ * A_];
__device__ float g_epart[8 * B_ * T_];     // per-N-chunk energy partials
__device__ float g_ctx_part[8 * B_ * E_];

// ---------------- PTX helpers (baseline ISA only: sm_80-class) ------------------
__device__ __forceinline__ u32 smem_u32(const void* p) {
    u32 a; asm("{ .reg .u64 t; cvta.to.shared.u64 t, %1; cvt.u32.u64 %0, t; }" : "=r"(a) : "l"(p));
    return a;
}
__device__ __forceinline__ void cpa16(u32 dst, const void* src) {
    asm volatile("cp.async.cg.shared.global [%0], [%1], 16;" :: "r"(dst), "l"(src));
}
#define CPA_COMMIT()  asm volatile("cp.async.commit_group;" ::: "memory")
#define CPA_WAIT(n)   asm volatile("cp.async.wait_group %0;" :: "n"(n) : "memory")

__device__ __forceinline__ void ldsm4(u32* r, u32 addr) {
    asm volatile("ldmatrix.sync.aligned.m8n8.x4.shared.b16 {%0,%1,%2,%3}, [%4];"
        : "=r"(r[0]), "=r"(r[1]), "=r"(r[2]), "=r"(r[3]) : "r"(addr));
}
__device__ __forceinline__ void mma_f16(float* c, const u32* a, const u32* b) {
    asm volatile("mma.sync.aligned.m16n8k16.row.col.f32.f16.f16.f32 "
        "{%0,%1,%2,%3}, {%4,%5,%6,%7}, {%8,%9}, {%0,%1,%2,%3};"
        : "+f"(c[0]), "+f"(c[1]), "+f"(c[2]), "+f"(c[3])
        : "r"(a[0]), "r"(a[1]), "r"(a[2]), "r"(a[3]), "r"(b[0]), "r"(b[1]));
}

// tanh via 2 MUFU: tanh(x) = (e - 1)/(e + 1), e = 2^(2x*log2e)
__device__ __forceinline__ float fast_tanh(float x) {
    float xa = fminf(fmaxf(x, -12.0f), 12.0f);
    float e;
    asm("ex2.approx.f32 %0, %1;" : "=f"(e) : "f"(xa * 2.8853900817779268f));
    float r;
    asm("rcp.approx.f32 %0, %1;" : "=f"(r) : "f"(e + 1.0f));
    return (e - 1.0f) * r;
}

// ---------------- pass 0a: enc fp32 -> fp16 (8 elems/thread, 16B store) ---------
__global__ __launch_bounds__(256) void convert_enc_kernel(const float* __restrict__ enc) {
    size_t i = ((size_t)blockIdx.x * 256 + threadIdx.x) * 8;
    float4 x = *(const float4*)(enc + i);
    float4 y = *(const float4*)(enc + i + 4);
    __half2 h[4] = { __floats2half2_rn(x.x, x.y), __floats2half2_rn(x.z, x.w),
                     __floats2half2_rn(y.x, y.y), __floats2half2_rn(y.z, y.w) };
    *(uint4*)(g_enc_h + i) = *(uint4*)h;
}

// ---------------- pass 0b: W_enc [E,A] -> W^T [A,E] fp16 (RN) -------------------
__global__ __launch_bounds__(256) void convert_wt_kernel(const float* __restrict__ W) {
    int idx = blockIdx.x * 256 + threadIdx.x;      // output-linear over [A,E]
    int a = idx >> 10, e = idx & 1023;
    g_Wt[idx] = __float2half_rn(W[(size_t)e * A_ + a]);
}

// ---------------- pass 1: dec_proj[b,a] = dec[b,:] . W_dec[:,a] + b_enc[a] ------
__global__ __launch_bounds__(256) void dec_proj_kernel(
    const float* __restrict__ dec_out, const float* __restrict__ W_dec,
    const float* __restrict__ b_enc)
{
    int b = blockIdx.y;
    int a = blockIdx.x * 256 + threadIdx.x;
    __shared__ float ds[D_];
    for (int i = threadIdx.x; i < D_; i += 256) ds[i] = dec_out[b * D_ + i];
    __syncthreads();
    float s = b_enc[a];
    #pragma unroll 8
    for (int d = 0; d < D_; ++d) s += ds[d] * W_dec[(size_t)d * A_ + a];
    g_dec_proj[b * A_ + a] = s;
}

// ---------------- pass 2: fp16 mma.sync GEMM, item-partitioned, KC=64 -----------
// R13 layout (best: 512 thr = 16 warps as 8M x 2N, warp tile 32x64) with KC=64
// stages: 16 stages/item instead of 32 => half the barrier/wait/refill overhead.
// Stage rows are 128B (8 granules of 16B), swizzle (g ^ (row&7))&7; the four
// K=16 sub-steps flip granule bits via off ^ (ks*32) (disjoint-bit XOR).
// Items (m-tile 256 rows, N-chunk 128): 2048 over a fixed 152-CTA grid.
// Depth-4 cp.async ring (always-commit), one __syncthreads per stage.
#define MT 256
#define NITEM 2048
#define GRID_E 152
#define NPIPE 4
#define ROWB 128
#define A_SZ (MT * ROWB)             // 32768
#define B_SZ (128 * ROWB)            // 16384
#define STG_SZ (A_SZ + B_SZ)         // 49152
#define ST_A 0
#define ST_B A_SZ
#define OF_V  (NPIPE * STG_SZ)       // 196608
#define OF_RED (OF_V + 4096)
#define SMEM_TOTAL (OF_RED + 2048)   // 202752 -> 1 CTA of 512 thr/SM

__global__ __launch_bounds__(512, 1) void energy_kernel(const float* __restrict__ v) {
    extern __shared__ char smem[];
    u32 sb = smem_u32(smem);
    const int tid  = threadIdx.x;
    const int lane = tid & 31, wid = tid >> 5;
    const int wm = wid >> 1, wn = wid & 1;       // 8M x 2N warp grid

    const u32 cta = blockIdx.x;
    const u32 w0 = (cta * NITEM) / GRID_E;
    const u32 w1 = ((cta + 1) * NITEM) / GRID_E;
    const u32 nst = (w1 - w0) * 16;

    float* v_s  = (float*)(smem + OF_V);
    float* red  = (float*)(smem + OF_RED);
    for (int i = tid; i < A_; i += 512) v_s[i] = v[i];

    // ---- per-thread constant addressing ----
    // stage_in: A = 2048 chunks (4/thread), B = 1024 chunks (2/thread)
    u32 soA[4], cgA[4], soB[2], cgB[2];
    #pragma unroll
    for (int r = 0; r < 4; ++r) {
        int c = tid + r * 512, row = c >> 3, g = c & 7;
        soA[r] = (u32)(row * ROWB + ((g ^ (row & 7)) & 7) * 16);
        cgA[r] = (u32)(row * 2048 + g * 16);
    }
    #pragma unroll
    for (int r = 0; r < 2; ++r) {
        int c = tid + r * 512, row = c >> 3, g = c & 7;
        soB[r] = (u32)(row * ROWB + ((g ^ (row & 7)) & 7) * 16);
        cgB[r] = (u32)(row * 2048 + g * 16);
    }

    // ldsm constants: offsets for ks=0; ks=1..3 = off ^ (ks*32)
    const u32 a_gbit = (u32)((lane >> 4) & 1);
    const u32 b_gbit = (u32)((lane >> 3) & 1);
    u32 loA[2], loB[4];
    #pragma unroll
    for (int tm = 0; tm < 2; ++tm) {
        int r = wm * 32 + (lane & 15) + tm * 16;
        loA[tm] = (u32)(r * ROWB) + ((a_gbit ^ ((u32)r & 7)) & 7) * 16;
    }
    #pragma unroll
    for (int p = 0; p < 4; ++p) {
        int r = wn * 64 + (lane & 7) + ((lane >> 4) & 1) * 8 + p * 16;
        loB[p] = (u32)(r * ROWB) + ((b_gbit ^ ((u32)r & 7)) & 7) * 16;
    }

    auto stage_in = [&](u32 f) {
        const u32 w  = w0 + (f >> 4);
        const u32 base = sb + (f & 3) * STG_SZ;
        const u32 kbyte = (f & 15) * 128;
        const char* encp = (const char*)g_enc_h + ((size_t)(w >> 3) << 19);
        const char* wp   = (const char*)g_Wt + ((size_t)(w & 7) << 18);
        #pragma unroll
        for (int r = 0; r < 4; ++r) cpa16(base + ST_A + soA[r], encp + cgA[r] + kbyte);
        #pragma unroll
        for (int r = 0; r < 2; ++r) cpa16(base + ST_B + soB[r], wp + cgB[r] + kbyte);
    };

    // prologue: fill pipeline depth-1 stages
    #pragma unroll
    for (u32 p = 0; p < NPIPE - 1; ++p) {
        stage_in(p);
        CPA_COMMIT();
    }

    for (u32 w = w0; w < w1; ++w) {
        const int m0 = (int)(w >> 3) << 8;
        const int ch = (int)(w & 7);
        const int b  = m0 >> 11;
        const int a0 = ch * 128;

        float c_[2][8][4];
        #pragma unroll
        for (int tm = 0; tm < 2; ++tm)
            #pragma unroll
            for (int tn = 0; tn < 8; ++tn)
                #pragma unroll
                for (int q = 0; q < 4; ++q) c_[tm][tn][q] = 0.f;

        for (u32 kc = 0; kc < 16; ++kc) {
            const u32 f = (w - w0) * 16 + kc;
            CPA_WAIT(2);                // stage f landed (always-commit keeps count exact)
            __syncthreads();            // frees refill target; orders red reuse

            if (f + NPIPE - 1 < nst) stage_in(f + NPIPE - 1);
            CPA_COMMIT();               // possibly-empty group keeps wait(2) exact

            const u32 baseA = sb + (f & 3) * STG_SZ + ST_A;
            const u32 baseB = sb + (f & 3) * STG_SZ + ST_B;
            #pragma unroll
            for (int ks = 0; ks < 4; ++ks) {
                const u32 kx = (u32)(ks * 32);   // granule flip: XOR bits 5-6
                u32 ah[2][4];
                #pragma unroll
                for (int tm = 0; tm < 2; ++tm)
                    ldsm4(ah[tm], baseA + (loA[tm] ^ kx));
                #pragma unroll
                for (int p = 0; p < 4; ++p) {
                    u32 tb[4];
                    ldsm4(tb, baseB + (loB[p] ^ kx));
                    #pragma unroll
                    for (int tm = 0; tm < 2; ++tm) {
                        mma_f16(c_[tm][2*p],   ah[tm], tb);
                        mma_f16(c_[tm][2*p+1], ah[tm], tb + 2);
                    }
                }
            }
        }

        // epilogue: tanh(c + dec_proj) . v ; dec_proj via direct L2-resident LDG
        float rowsum[4] = {0.f, 0.f, 0.f, 0.f};
        const int nbase = a0 + wn * 64 + 2 * (lane & 3);
        #pragma unroll
        for (int tn = 0; tn < 8; ++tn) {
            int n = nbase + tn * 8;
            float2 d = *(const float2*)&g_dec_proj[b * A_ + n];
            float2 vv = *(const float2*)&v_s[n];
            #pragma unroll
            for (int tm = 0; tm < 2; ++tm) {
                rowsum[tm*2+0] += fast_tanh(c_[tm][tn][0] + d.x) * vv.x
                                + fast_tanh(c_[tm][tn][1] + d.y) * vv.y;
                rowsum[tm*2+1] += fast_tanh(c_[tm][tn][2] + d.x) * vv.x
                                + fast_tanh(c_[tm][tn][3] + d.y) * vv.y;
            }
        }
        #pragma unroll
        for (int i = 0; i < 4; ++i) {
            float s = rowsum[i];
            s += __shfl_xor_sync(0xffffffffu, s, 1);
            s += __shfl_xor_sync(0xffffffffu, s, 2);
            rowsum[i] = s;
        }
        if ((lane & 3) == 0) {
            int r0 = lane >> 2;
            int rb = wn * 256 + wm * 32;
            red[rb + r0]          = rowsum[0];
            red[rb + r0 + 8]      = rowsum[1];
            red[rb + 16 + r0]     = rowsum[2];
            red[rb + 16 + r0 + 8] = rowsum[3];
        }
        __syncthreads();
        if (tid < 256)
            g_epart[ch * (B_ * T_) + m0 + tid] = red[tid] + red[256 + tid];
    }
}

// ---------------- pass 3: sum chunk partials + masked (0/1) softmax -------------
__global__ __launch_bounds__(256) void softmax_kernel(
    const int* __restrict__ x_lens, float* __restrict__ att)
{
    int b = blockIdx.x, tid = threadIdx.x;
    __shared__ float sm[T_];
    __shared__ float red[256];
    int len = x_lens[b];

    float mx = -3.4e38f;
    for (int t = tid; t < T_; t += 256) {
        int r = b * T_ + t;
        float e = 0.f;
        #pragma unroll
        for (int ch = 0; ch < 8; ++ch) e += g_epart[ch * (B_ * T_) + r];
        e = (t < len) ? e : 0.0f;      // reference multiplies by 0/1 mask
        sm[t] = e;
        mx = fmaxf(mx, e);
    }
    red[tid] = mx; __syncthreads();
    for (int s = 128; s > 0; s >>= 1) {
        if (tid < s) red[tid] = fmaxf(red[tid], red[tid + s]);
        __syncthreads();
    }
    mx = red[0];
    __syncthreads();

    float lsum = 0.f;
    for (int t = tid; t < T_; t += 256) {
        float e = expf(sm[t] - mx);
        sm[t] = e;
        lsum += e;
    }
    red[tid] = lsum; __syncthreads();
    for (int s = 128; s > 0; s >>= 1) {
        if (tid < s) red[tid] += red[tid + s];
        __syncthreads();
    }
    float inv = 1.0f / red[0];
    for (int t = tid; t < T_; t += 256) att[b * T_ + t] = sm[t] * inv;
}

// ---------------- pass 4: context partials over 8 T-segments (fp16 enc) ---------
__global__ __launch_bounds__(256) void context_part_kernel(const float* __restrict__ att) {
    int b = blockIdx.y, seg = blockIdx.z;
    int e2 = threadIdx.x;                        // + 256 for second column
    __shared__ float as_[T_ / 8];
    int t0 = seg * (T_ / 8);
    as_[threadIdx.x] = att[b * T_ + t0 + threadIdx.x];
    __syncthreads();
    const __half2* ep = (const __half2*)g_enc_h + ((size_t)b * T_ + t0) * (E_ / 2);
    float s0 = 0.f, s1 = 0.f, s2 = 0.f, s3 = 0.f;
    #pragma unroll 8
    for (int t = 0; t < T_ / 8; ++t) {
        const __half2* row = ep + (size_t)t * (E_ / 2);
        float2 f0 = __half22float2(row[e2]);
        float2 f1 = __half22float2(row[e2 + 256]);
        float a = as_[t];
        s0 += f0.x * a; s1 += f0.y * a;
        s2 += f1.x * a; s3 += f1.y * a;
    }
    float2* out = (float2*)&g_ctx_part[((size_t)seg * B_ + b) * E_];
    out[e2]       = make_float2(s0, s1);
    out[e2 + 256] = make_float2(s2, s3);
}

__global__ __launch_bounds__(256) void context_reduce_kernel(float* __restrict__ ctx) {
    int i = blockIdx.x * 256 + threadIdx.x;      // over B_*E_
    float s = 0.f;
    #pragma unroll
    for (int seg = 0; seg < 8; ++seg) s += g_ctx_part[seg * (B_ * E_) + i];
    ctx[i] = s;
}

// ---------------- launch -------------------------------------------------------
extern "C" void kernel_launch(void* const* d_in, const int* in_sizes, int n_in,
                              void* d_out, int out_size)
{
    const float* enc     = (const float*)d_in[0];  // [B,T,E]
    const int*   x_lens  = (const int*)  d_in[1];  // [B]
    const float* dec_out = (const float*)d_in[2];  // [B,1,D]
    // d_in[3] att_weights_step: unused by reference
    const float* W_enc   = (const float*)d_in[4];  // [E,A]
    const float* b_enc   = (const float*)d_in[5];  // [A]
    const float* W_dec   = (const float*)d_in[6];  // [D,A]
    const float* v       = (const float*)d_in[7];  // [A]

    float* ctx = (float*)d_out;            // [B,1,E]
    float* att = (float*)d_out + B_ * E_;  // [B,T]

    cudaFuncSetAttribute(energy_kernel,
                         cudaFuncAttributeMaxDynamicSharedMemorySize, SMEM_TOTAL);

    convert_enc_kernel<<<(B_ * T_ * E_) / (256 * 8), 256>>>(enc);
    convert_wt_kernel <<<(A_ * E_) / 256, 256>>>(W_enc);
    dec_proj_kernel   <<<dim3(A_ / 256, B_), 256>>>(dec_out, W_dec, b_enc);
    energy_kernel     <<<GRID_E, 512, SMEM_TOTAL>>>(v);
    softmax_kernel    <<<B_, 256>>>(x_lens, att);
    context_part_kernel<<<dim3(1, B_, 8), 256>>>(att);
    context_reduce_kernel<<<(B_ * E_) / 256, 256>>>(ctx);
}

// round 16
// speedup vs baseline: 1.1447x; 1.0119x over previous
#include <cuda_runtime.h>
#include <cuda_fp16.h>
#include <math.h>
#include <stdint.h>

#define B_ 32
#define T_ 2048
#define E_ 1024
#define A_ 1024
#define D_ 1024

typedef unsigned int u32;
typedef unsigned long long u64;

// ---------------- scratch (device globals; allocations forbidden) --------------
__device__ __align__(256) __half g_enc_h[(size_t)B_ * T_ * E_];  // enc fp16
__device__ __align__(256) __half g_Wt[A_ * E_];                  // W^T [A,E] fp16
__device__ float g_dec_proj[B_ * A_];
__device__ float g_epart[8 * B_ * T_];     // per-N-chunk energy partials
__device__ float g_ctx_part[8 * B_ * E_];

// ---------------- PTX helpers (baseline ISA only: sm_80-class) ------------------
__device__ __forceinline__ u32 smem_u32(const void* p) {
    u32 a; asm("{ .reg .u64 t; cvta.to.shared.u64 t, %1; cvt.u32.u64 %0, t; }" : "=r"(a) : "l"(p));
    return a;
}
__device__ __forceinline__ void cpa16(u32 dst, const void* src) {
    asm volatile("cp.async.cg.shared.global [%0], [%1], 16;" :: "r"(dst), "l"(src));
}
#define CPA_COMMIT()  asm volatile("cp.async.commit_group;" ::: "memory")
#define CPA_WAIT(n)   asm volatile("cp.async.wait_group %0;" :: "n"(n) : "memory")

__device__ __forceinline__ void ldsm4(u32* r, u32 addr) {
    asm volatile("ldmatrix.sync.aligned.m8n8.x4.shared.b16 {%0,%1,%2,%3}, [%4];"
        : "=r"(r[0]), "=r"(r[1]), "=r"(r[2]), "=r"(r[3]) : "r"(addr));
}
__device__ __forceinline__ void mma_f16(float* c, const u32* a, const u32* b) {
    asm volatile("mma.sync.aligned.m16n8k16.row.col.f32.f16.f16.f32 "
        "{%0,%1,%2,%3}, {%4,%5,%6,%7}, {%8,%9}, {%0,%1,%2,%3};"
        : "+f"(c[0]), "+f"(c[1]), "+f"(c[2]), "+f"(c[3])
        : "r"(a[0]), "r"(a[1]), "r"(a[2]), "r"(a[3]), "r"(b[0]), "r"(b[1]));
}

// tanh via 2 MUFU: tanh(x) = (e - 1)/(e + 1), e = 2^(2x*log2e)
__device__ __forceinline__ float fast_tanh(float x) {
    float xa = fminf(fmaxf(x, -12.0f), 12.0f);
    float e;
    asm("ex2.approx.f32 %0, %1;" : "=f"(e) : "f"(xa * 2.8853900817779268f));
    float r;
    asm("rcp.approx.f32 %0, %1;" : "=f"(r) : "f"(e + 1.0f));
    return (e - 1.0f) * r;
}

// ---------------- pass 0a: enc fp32 -> fp16 (8 elems/thread, 16B store) ---------
__global__ __launch_bounds__(256) void convert_enc_kernel(const float* __restrict__ enc) {
    size_t i = ((size_t)blockIdx.x * 256 + threadIdx.x) * 8;
    float4 x = *(const float4*)(enc + i);
    float4 y = *(const float4*)(enc + i + 4);
    __half2 h[4] = { __floats2half2_rn(x.x, x.y), __floats2half2_rn(x.z, x.w),
                     __floats2half2_rn(y.x, y.y), __floats2half2_rn(y.z, y.w) };
    *(uint4*)(g_enc_h + i) = *(uint4*)h;
}

// ---------------- pass 0b+1 fused: W^T convert, then dec_proj -------------------
// blocks [0, 4096): W_enc [E,A] -> W^T [A,E] fp16.
// blocks [4096, 4224): dec_proj[b,a] = dec[b,:] . W_dec[:,a] + b_enc[a] (fp32).
__global__ __launch_bounds__(256) void prep_kernel(
    const float* __restrict__ W, const float* __restrict__ dec_out,
    const float* __restrict__ W_dec, const float* __restrict__ b_enc)
{
    int blk = blockIdx.x;
    if (blk < 4096) {
        int idx = blk * 256 + threadIdx.x;         // output-linear over [A,E]
        int a = idx >> 10, e = idx & 1023;
        g_Wt[idx] = __float2half_rn(W[(size_t)e * A_ + a]);
    } else {
        int q = blk - 4096;                        // q = bq*4 + aq
        int b = q >> 2;
        int a = (q & 3) * 256 + threadIdx.x;
        __shared__ float ds[D_];
        for (int i = threadIdx.x; i < D_; i += 256) ds[i] = dec_out[b * D_ + i];
        __syncthreads();
        float s = b_enc[a];
        #pragma unroll 8
        for (int d = 0; d < D_; ++d) s += ds[d] * W_dec[(size_t)d * A_ + a];
        g_dec_proj[b * A_ + a] = s;
    }
}

// ---------------- pass 2: fp16 mma.sync GEMM, item-partitioned, KC=128 ----------
// 512 thr = 16 warps as 8M x 2N (warp tile 32x64). KC=128 stages: 8 stages/item
// (half of R15's 16) => half the barrier/wait/refill overhead again. Stage rows
// are 256B (16 granules of 16B), swizzle g ^ (row&7); the eight K=16 sub-steps
// flip granule bits via off ^ (ks*32) (disjoint-bit XOR). Depth-2 ring, ONE
// __syncthreads per stage (barrier at stage s proves stage s-1's reads done =
// exactly the buffer stage s+1 refills). Items (m-tile 256 rows, N-chunk 128):
// 2048 over a fixed 152-CTA grid.
#define MT 256
#define NITEM 2048
#define GRID_E 152
#define NPIPE 2
#define ROWB 256
#define A_SZ (MT * ROWB)             // 65536
#define B_SZ (128 * ROWB)            // 32768
#define STG_SZ (A_SZ + B_SZ)         // 98304
#define ST_A 0
#define ST_B A_SZ
#define OF_V  (NPIPE * STG_SZ)       // 196608
#define OF_RED (OF_V + 4096)
#define SMEM_TOTAL (OF_RED + 2048)   // 202752 -> 1 CTA of 512 thr/SM

__global__ __launch_bounds__(512, 1) void energy_kernel(const float* __restrict__ v) {
    extern __shared__ char smem[];
    u32 sb = smem_u32(smem);
    const int tid  = threadIdx.x;
    const int lane = tid & 31, wid = tid >> 5;
    const int wm = wid >> 1, wn = wid & 1;       // 8M x 2N warp grid

    const u32 cta = blockIdx.x;
    const u32 w0 = (cta * NITEM) / GRID_E;
    const u32 w1 = ((cta + 1) * NITEM) / GRID_E;
    const u32 nst = (w1 - w0) * 8;

    float* v_s  = (float*)(smem + OF_V);
    float* red  = (float*)(smem + OF_RED);
    for (int i = tid; i < A_; i += 512) v_s[i] = v[i];

    // ---- per-thread constant addressing ----
    // stage_in: A = 4096 chunks (8/thread), B = 2048 chunks (4/thread); 16 gran/row
    u32 soA[8], cgA[8], soB[4], cgB[4];
    #pragma unroll
    for (int r = 0; r < 8; ++r) {
        int c = tid + r * 512, row = c >> 4, g = c & 15;
        soA[r] = (u32)(row * ROWB + (g ^ (row & 7)) * 16);
        cgA[r] = (u32)(row * 2048 + g * 16);
    }
    #pragma unroll
    for (int r = 0; r < 4; ++r) {
        int c = tid + r * 512, row = c >> 4, g = c & 15;
        soB[r] = (u32)(row * ROWB + (g ^ (row & 7)) * 16);
        cgB[r] = (u32)(row * 2048 + g * 16);
    }

    // ldsm constants: offsets for ks=0; ks=1..7 => off ^ (ks*32)
    const u32 a_gbit = (u32)((lane >> 4) & 1);
    const u32 b_gbit = (u32)((lane >> 3) & 1);
    u32 loA[2], loB[4];
    #pragma unroll
    for (int tm = 0; tm < 2; ++tm) {
        int r = wm * 32 + (lane & 15) + tm * 16;
        loA[tm] = (u32)(r * ROWB) + ((a_gbit ^ ((u32)r & 7)) & 15) * 16;
    }
    #pragma unroll
    for (int p = 0; p < 4; ++p) {
        int r = wn * 64 + (lane & 7) + ((lane >> 4) & 1) * 8 + p * 16;
        loB[p] = (u32)(r * ROWB) + ((b_gbit ^ ((u32)r & 7)) & 15) * 16;
    }

    auto stage_in = [&](u32 f) {
        const u32 w  = w0 + (f >> 3);
        const u32 base = sb + (f & 1) * STG_SZ;
        const u32 kbyte = (f & 7) * 256;
        const char* encp = (const char*)g_enc_h + ((size_t)(w >> 3) << 19);
        const char* wp   = (const char*)g_Wt + ((size_t)(w & 7) << 18);
        #pragma unroll
        for (int r = 0; r < 8; ++r) cpa16(base + ST_A + soA[r], encp + cgA[r] + kbyte);
        #pragma unroll
        for (int r = 0; r < 4; ++r) cpa16(base + ST_B + soB[r], wp + cgB[r] + kbyte);
    };

    // prologue: fill depth-1 stage
    stage_in(0);
    CPA_COMMIT();

    for (u32 w = w0; w < w1; ++w) {
        const int m0 = (int)(w >> 3) << 8;
        const int ch = (int)(w & 7);
        const int b  = m0 >> 11;
        const int a0 = ch * 128;

        float c_[2][8][4];
        #pragma unroll
        for (int tm = 0; tm < 2; ++tm)
            #pragma unroll
            for (int tn = 0; tn < 8; ++tn)
                #pragma unroll
                for (int q = 0; q < 4; ++q) c_[tm][tn][q] = 0.f;

        for (u32 kc = 0; kc < 8; ++kc) {
            const u32 f = (w - w0) * 8 + kc;
            CPA_WAIT(0);                // stage f landed
            __syncthreads();            // proves stage f-1 reads done -> buf free

            if (f + 1 < nst) stage_in(f + 1);
            CPA_COMMIT();               // possibly-empty group keeps count exact

            const u32 baseA = sb + (f & 1) * STG_SZ + ST_A;
            const u32 baseB = sb + (f & 1) * STG_SZ + ST_B;
            #pragma unroll
            for (int ks = 0; ks < 8; ++ks) {
                const u32 kx = (u32)(ks * 32);   // granule flip (bits 5-7)
                u32 ah[2][4];
                #pragma unroll
                for (int tm = 0; tm < 2; ++tm)
                    ldsm4(ah[tm], baseA + (loA[tm] ^ kx));
                #pragma unroll
                for (int p = 0; p < 4; ++p) {
                    u32 tb[4];
                    ldsm4(tb, baseB + (loB[p] ^ kx));
                    #pragma unroll
                    for (int tm = 0; tm < 2; ++tm) {
                        mma_f16(c_[tm][2*p],   ah[tm], tb);
                        mma_f16(c_[tm][2*p+1], ah[tm], tb + 2);
                    }
                }
            }
        }

        // epilogue: tanh(c + dec_proj) . v ; dec_proj via direct L2-resident LDG
        float rowsum[4] = {0.f, 0.f, 0.f, 0.f};
        const int nbase = a0 + wn * 64 + 2 * (lane & 3);
        #pragma unroll
        for (int tn = 0; tn < 8; ++tn) {
            int n = nbase + tn * 8;
            float2 d = *(const float2*)&g_dec_proj[b * A_ + n];
            float2 vv = *(const float2*)&v_s[n];
            #pragma unroll
            for (int tm = 0; tm < 2; ++tm) {
                rowsum[tm*2+0] += fast_tanh(c_[tm][tn][0] + d.x) * vv.x
                                + fast_tanh(c_[tm][tn][1] + d.y) * vv.y;
                rowsum[tm*2+1] += fast_tanh(c_[tm][tn][2] + d.x) * vv.x
                                + fast_tanh(c_[tm][tn][3] + d.y) * vv.y;
            }
        }
        #pragma unroll
        for (int i = 0; i < 4; ++i) {
            float s = rowsum[i];
            s += __shfl_xor_sync(0xffffffffu, s, 1);
            s += __shfl_xor_sync(0xffffffffu, s, 2);
            rowsum[i] = s;
        }
        if ((lane & 3) == 0) {
            int r0 = lane >> 2;
            int rb = wn * 256 + wm * 32;
            red[rb + r0]          = rowsum[0];
            red[rb + r0 + 8]      = rowsum[1];
            red[rb + 16 + r0]     = rowsum[2];
            red[rb + 16 + r0 + 8] = rowsum[3];
        }
        __syncthreads();
        if (tid < 256)
            g_epart[ch * (B_ * T_) + m0 + tid] = red[tid] + red[256 + tid];
    }
}

// ---------------- pass 3: sum chunk partials + masked (0/1) softmax -------------
__global__ __launch_bounds__(256) void softmax_kernel(
    const int* __restrict__ x_lens, float* __restrict__ att)
{
    int b = blockIdx.x, tid = threadIdx.x;
    __shared__ float sm[T_];
    __shared__ float red[256];
    int len = x_lens[b];

    float mx = -3.4e38f;
    for (int t = tid; t < T_; t += 256) {
        int r = b * T_ + t;
        float e = 0.f;
        #pragma unroll
        for (int ch = 0; ch < 8; ++ch) e += g_epart[ch * (B_ * T_) + r];
        e = (t < len) ? e : 0.0f;      // reference multiplies by 0/1 mask
        sm[t] = e;
        mx = fmaxf(mx, e);
    }
    red[tid] = mx; __syncthreads();
    for (int s = 128; s > 0; s >>= 1) {
        if (tid < s) red[tid] = fmaxf(red[tid], red[tid + s]);
        __syncthreads();
    }
    mx = red[0];
    __syncthreads();

    float lsum = 0.f;
    for (int t = tid; t < T_; t += 256) {
        float e = expf(sm[t] - mx);
        sm[t] = e;
        lsum += e;
    }
    red[tid] = lsum; __syncthreads();
    for (int s = 128; s > 0; s >>= 1) {
        if (tid < s) red[tid] += red[tid + s];
        __syncthreads();
    }
    float inv = 1.0f / red[0];
    for (int t = tid; t < T_; t += 256) att[b * T_ + t] = sm[t] * inv;
}

// ---------------- pass 4: context partials over 8 T-segments (fp16 enc) ---------
__global__ __launch_bounds__(256) void context_part_kernel(const float* __restrict__ att) {
    int b = blockIdx.y, seg = blockIdx.z;
    int e2 = threadIdx.x;                        // + 256 for second column
    __shared__ float as_[T_ / 8];
    int t0 = seg * (T_ / 8);
    as_[threadIdx.x] = att[b * T_ + t0 + threadIdx.x];
    __syncthreads();
    const __half2* ep = (const __half2*)g_enc_h + ((size_t)b * T_ + t0) * (E_ / 2);
    float s0 = 0.f, s1 = 0.f, s2 = 0.f, s3 = 0.f;
    #pragma unroll 8
    for (int t = 0; t < T_ / 8; ++t) {
        const __half2* row = ep + (size_t)t * (E_ / 2);
        float2 f0 = __half22float2(row[e2]);
        float2 f1 = __half22float2(row[e2 + 256]);
        float a = as_[t];
        s0 += f0.x * a; s1 += f0.y * a;
        s2 += f1.x * a; s3 += f1.y * a;
    }
    float2* out = (float2*)&g_ctx_part[((size_t)seg * B_ + b) * E_];
    out[e2]       = make_float2(s0, s1);
    out[e2 + 256] = make_float2(s2, s3);
}

__global__ __launch_bounds__(256) void context_reduce_kernel(float* __restrict__ ctx) {
    int i = blockIdx.x * 256 + threadIdx.x;      // over B_*E_
    float s = 0.f;
    #pragma unroll
    for (int seg = 0; seg < 8; ++seg) s += g_ctx_part[seg * (B_ * E_) + i];
    ctx[i] = s;
}

// ---------------- launch -------------------------------------------------------
extern "C" void kernel_launch(void* const* d_in, const int* in_sizes, int n_in,
                              void* d_out, int out_size)
{
    const float* enc     = (const float*)d_in[0];  // [B,T,E]
    const int*   x_lens  = (const int*)  d_in[1];  // [B]
    const float* dec_out = (const float*)d_in[2];  // [B,1,D]
    // d_in[3] att_weights_step: unused by reference
    const float* W_enc   = (const float*)d_in[4];  // [E,A]
    const float* b_enc   = (const float*)d_in[5];  // [A]
    const float* W_dec   = (const float*)d_in[6];  // [D,A]
    const float* v       = (const float*)d_in[7];  // [A]

    float* ctx = (float*)d_out;            // [B,1,E]
    float* att = (float*)d_out + B_ * E_;  // [B,T]

    cudaFuncSetAttribute(energy_kernel,
                         cudaFuncAttributeMaxDynamicSharedMemorySize, SMEM_TOTAL);

    convert_enc_kernel<<<(B_ * T_ * E_) / (256 * 8), 256>>>(enc);
    prep_kernel       <<<4096 + 128, 256>>>(W_enc, dec_out, W_dec, b_enc);
    energy_kernel     <<<GRID_E, 512, SMEM_TOTAL>>>(v);
    softmax_kernel    <<<B_, 256>>>(x_lens, att);
    context_part_kernel<<<dim3(1, B_, 8), 256>>>(att);
    context_reduce_kernel<<<(B_ * E_) / 256, 256>>>(ctx);
}